// round 6
// baseline (speedup 1.0000x reference)
#include <cuda_runtime.h>
#include <math.h>

#define Nn   100000
#define Ee   1600000
#define FIN  128
#define HH   64
#define GG   256
#define NEG_INF __int_as_float(0xff800000)

typedef unsigned long long u64;

// ---------------- f32x2 helpers (PTX-only; ptxas never auto-fuses) ----------------
__device__ __forceinline__ u64 pack2(float lo, float hi) {
    u64 r; asm("mov.b64 %0, {%1, %2};" : "=l"(r) : "f"(lo), "f"(hi)); return r;
}
__device__ __forceinline__ void fma2(u64& d, u64 a, u64 b) {
    asm("fma.rn.f32x2 %0, %1, %2, %0;" : "+l"(d) : "l"(a), "l"(b));
}
__device__ __forceinline__ float2 unpack2(u64 v) {
    float2 f; asm("mov.b64 {%0, %1}, %2;" : "=f"(f.x), "=f"(f.y) : "l"(v)); return f;
}

// ---------------- device scratch ----------------
__device__ int   g_deg[Nn];
__device__ int   g_rowptr[Nn];
__device__ int   g_fill[Nn];
__device__ int   g_csr[Ee];
__device__ int   g_bsum[128];
__device__ float g_h1[(size_t)Nn * HH];
__device__ float g_h2[(size_t)Nn * HH];
__device__ float g_h3[(size_t)Nn * HH];
__device__ float g_c[Nn];
__device__ float g_e[Nn];

__device__ __forceinline__ float4 max4(float4 a, float4 b) {
    return make_float4(fmaxf(a.x, b.x), fmaxf(a.y, b.y), fmaxf(a.z, b.z), fmaxf(a.w, b.w));
}
__device__ __forceinline__ float2 max2(float2 a, float2 b) {
    return make_float2(fmaxf(a.x, b.x), fmaxf(a.y, b.y));
}

// ---------------- CSR build ----------------
__global__ void zero_deg_kernel() {
    int i = blockIdx.x * blockDim.x + threadIdx.x;
    if (i < Nn) g_deg[i] = 0;
}

__global__ void hist_kernel(const int* __restrict__ ei) {
    int e = blockIdx.x * blockDim.x + threadIdx.x;
    if (e < Ee) atomicAdd(&g_deg[__ldg(&ei[Ee + e])], 1);
}

__global__ void scan_a_kernel() {
    __shared__ int wsum[32];
    int tid = threadIdx.x;
    int i = blockIdx.x * 1024 + tid;
    int v = (i < Nn) ? g_deg[i] : 0;
    int lane = tid & 31, wid = tid >> 5;
    int x = v;
#pragma unroll
    for (int o = 1; o < 32; o <<= 1) {
        int y = __shfl_up_sync(0xffffffffu, x, o);
        if (lane >= o) x += y;
    }
    if (lane == 31) wsum[wid] = x;
    __syncthreads();
    if (wid == 0) {
        int w = wsum[lane];
        int xx = w;
#pragma unroll
        for (int o = 1; o < 32; o <<= 1) {
            int y = __shfl_up_sync(0xffffffffu, xx, o);
            if (lane >= o) xx += y;
        }
        wsum[lane] = xx - w;
    }
    __syncthreads();
    int excl = x - v + wsum[wid];
    if (i < Nn) g_rowptr[i] = excl;
    if (tid == 1023) g_bsum[blockIdx.x] = excl + v;
}

__global__ void scan_c_kernel(int nb) {
    __shared__ int ws[4];
    __shared__ int soff;
    int tid = threadIdx.x;
    if (tid < 128) {
        int v = (tid < nb && tid < blockIdx.x) ? g_bsum[tid] : 0;
#pragma unroll
        for (int o = 16; o > 0; o >>= 1) v += __shfl_down_sync(0xffffffffu, v, o);
        if ((tid & 31) == 0) ws[tid >> 5] = v;
    }
    __syncthreads();
    if (tid == 0) soff = ws[0] + ws[1] + ws[2] + ws[3];
    __syncthreads();
    int i = blockIdx.x * 1024 + tid;
    if (i < Nn) {
        int r = g_rowptr[i] + soff;
        g_rowptr[i] = r;
        g_fill[i] = r;
    }
}

__global__ void csr_scatter_kernel(const int* __restrict__ ei) {
    int e = blockIdx.x * blockDim.x + threadIdx.x;
    if (e >= Ee) return;
    int src = __ldg(&ei[e]);
    int dst = __ldg(&ei[Ee + e]);
    int pos = atomicAdd(&g_fill[dst], 1);
    g_csr[pos] = src;
}

// ---------------- fused layer: neighbor-max gather + SAGE GEMM ----------------
// Block: 256 threads, 64 nodes x 64 out-feats.
// Phase A: warp w gathers max over neighbors for nodes node0+w*8..+7 into sA,
//          and stages self-features into sX (full K resident in dynamic smem).
// Phase B: f32x2 GEMM: out = relu(sA @ Wl + sX @ Wr + b).
template <int K>
__global__ void __launch_bounds__(256)
fused_sage_layer(const float* __restrict__ xin,
                 const float* __restrict__ Wl, const float* __restrict__ blv,
                 const float* __restrict__ Wr, float* __restrict__ out) {
    constexpr int STRIDE = K + 4;
    extern __shared__ float smem[];
    float* sA = smem;                 // [64][STRIDE]
    float* sX = smem + 64 * STRIDE;   // [64][STRIDE]

    const int tid = threadIdx.x;
    const int lane = tid & 31;
    const int wid = tid >> 5;
    const int node0 = blockIdx.x * 64;

    // ---- Phase A1: stage self-features (coalesced float4) ----
#pragma unroll
    for (int t = tid; t < 64 * (K / 4); t += 256) {
        int nn = t / (K / 4);
        int ck = t % (K / 4);
        int node = node0 + nn;
        float4 xv = make_float4(0.f, 0.f, 0.f, 0.f);
        if (node < Nn) xv = *(const float4*)&xin[(size_t)node * K + ck * 4];
        *(float4*)&sX[nn * STRIDE + ck * 4] = xv;
    }

    // ---- Phase A2: gather neighbor max into sA (warp per 8 nodes) ----
#pragma unroll 1
    for (int nl = 0; nl < 8; nl++) {
        int nn = wid * 8 + nl;
        int node = node0 + nn;
        if (node >= Nn) {
            if (K == 128) *(float4*)&sA[nn * STRIDE + lane * 4] = make_float4(0.f, 0.f, 0.f, 0.f);
            else          *(float2*)&sA[nn * STRIDE + lane * 2] = make_float2(0.f, 0.f);
            continue;
        }
        int start = g_rowptr[node];
        int d = g_deg[node];
        if (K == 128) {
            const float4* x4 = (const float4*)xin;
            float4 m = make_float4(NEG_INF, NEG_INF, NEG_INF, NEG_INF);
            int i = 0;
            for (; i + 8 <= d; i += 8) {
                int idx[8];
#pragma unroll
                for (int j = 0; j < 8; j++) idx[j] = g_csr[start + i + j];
                float4 v[8];
#pragma unroll
                for (int j = 0; j < 8; j++) v[j] = __ldg(&x4[(size_t)idx[j] * 32 + lane]);
#pragma unroll
                for (int j = 0; j < 8; j++) m = max4(m, v[j]);
            }
            if (i + 4 <= d) {
                int idx[4];
#pragma unroll
                for (int j = 0; j < 4; j++) idx[j] = g_csr[start + i + j];
                float4 v[4];
#pragma unroll
                for (int j = 0; j < 4; j++) v[j] = __ldg(&x4[(size_t)idx[j] * 32 + lane]);
#pragma unroll
                for (int j = 0; j < 4; j++) m = max4(m, v[j]);
                i += 4;
            }
            for (; i < d; i++)
                m = max4(m, __ldg(&x4[(size_t)g_csr[start + i] * 32 + lane]));
            if (d == 0) m = make_float4(0.f, 0.f, 0.f, 0.f);
            *(float4*)&sA[nn * STRIDE + lane * 4] = m;
        } else {
            const float2* x2 = (const float2*)xin;
            float2 m = make_float2(NEG_INF, NEG_INF);
            int i = 0;
            for (; i + 8 <= d; i += 8) {
                int idx[8];
#pragma unroll
                for (int j = 0; j < 8; j++) idx[j] = g_csr[start + i + j];
                float2 v[8];
#pragma unroll
                for (int j = 0; j < 8; j++) v[j] = __ldg(&x2[(size_t)idx[j] * 32 + lane]);
#pragma unroll
                for (int j = 0; j < 8; j++) m = max2(m, v[j]);
            }
            if (i + 4 <= d) {
                int idx[4];
#pragma unroll
                for (int j = 0; j < 4; j++) idx[j] = g_csr[start + i + j];
                float2 v[4];
#pragma unroll
                for (int j = 0; j < 4; j++) v[j] = __ldg(&x2[(size_t)idx[j] * 32 + lane]);
#pragma unroll
                for (int j = 0; j < 4; j++) m = max2(m, v[j]);
                i += 4;
            }
            for (; i < d; i++)
                m = max2(m, __ldg(&x2[(size_t)g_csr[start + i] * 32 + lane]));
            if (d == 0) m = make_float2(0.f, 0.f);
            *(float2*)&sA[nn * STRIDE + lane * 2] = m;
        }
    }
    __syncthreads();

    // ---- Phase B: GEMM (f32x2) ----
    const int tx = tid & 15;    // out-feature group j = tx*4..+3
    const int ty = tid >> 4;    // node group n = ty*4..+3

    u64 acc[4][2];
#pragma unroll
    for (int i = 0; i < 4; i++) { acc[i][0] = 0ULL; acc[i][1] = 0ULL; }

#pragma unroll 8
    for (int kk = 0; kk < K; kk++) {
        const ulonglong2 wl2 = *(const ulonglong2*)&Wl[(size_t)kk * 64 + tx * 4];
        const ulonglong2 wr2 = *(const ulonglong2*)&Wr[(size_t)kk * 64 + tx * 4];
#pragma unroll
        for (int i = 0; i < 4; i++) {
            float a  = sA[(ty * 4 + i) * STRIDE + kk];
            float xv = sX[(ty * 4 + i) * STRIDE + kk];
            u64 a2 = pack2(a, a);
            u64 x2 = pack2(xv, xv);
            fma2(acc[i][0], a2, wl2.x);
            fma2(acc[i][1], a2, wl2.y);
            fma2(acc[i][0], x2, wr2.x);
            fma2(acc[i][1], x2, wr2.y);
        }
    }

    const float4 b4 = *(const float4*)&blv[tx * 4];
#pragma unroll
    for (int i = 0; i < 4; i++) {
        int node = node0 + ty * 4 + i;
        if (node < Nn) {
            float2 lo = unpack2(acc[i][0]);
            float2 hi = unpack2(acc[i][1]);
            float4 o;
            o.x = fmaxf(lo.x + b4.x, 0.f);
            o.y = fmaxf(lo.y + b4.y, 0.f);
            o.z = fmaxf(hi.x + b4.z, 0.f);
            o.w = fmaxf(hi.y + b4.w, 0.f);
            *(float4*)&out[(size_t)node * 64 + tx * 4] = o;
        }
    }
}

// ---------------- fused attention pooling: one block per graph ----------------
__global__ void __launch_bounds__(256)
fused_pool_kernel(const float4* __restrict__ clo4, const float* __restrict__ Wc,
                  const float* __restrict__ bc, const int* __restrict__ batch,
                  const float* __restrict__ h3,
                  const float* __restrict__ Wa1, const float* __restrict__ ba1,
                  const float* __restrict__ Wa2, const float* __restrict__ ba2,
                  float* __restrict__ out) {
    const int g = blockIdx.x;
    const int tid = threadIdx.x;
    const int lane = tid & 31, wid = tid >> 5;

    __shared__ int sS, sE;
    __shared__ float red[32];
    __shared__ float s_bcast;
    __shared__ float pooled[64];

    if (tid == 0) {
        int lo = 0, hi = Nn;
        while (lo < hi) { int mid = (lo + hi) >> 1; if (batch[mid] < g) lo = mid + 1; else hi = mid; }
        sS = lo;
        hi = Nn;
        while (lo < hi) { int mid = (lo + hi) >> 1; if (batch[mid] < g + 1) lo = mid + 1; else hi = mid; }
        sE = lo;
    }
    __syncthreads();
    const int s = sS, e = sE;
    const int count = e - s;

    float wc[16];
#pragma unroll
    for (int q = 0; q < 16; q++) wc[q] = Wc[q];
    float bias = bc[0];

    float lmax = NEG_INF;
    for (int i = s + tid; i < e; i += 256) {
        float cv = bias;
#pragma unroll
        for (int q = 0; q < 4; q++) {
            float4 c4 = __ldg(&clo4[(size_t)i * 4 + q]);
            cv += c4.x * wc[q * 4 + 0] + c4.y * wc[q * 4 + 1] + c4.z * wc[q * 4 + 2] + c4.w * wc[q * 4 + 3];
        }
        g_c[i] = cv;
        lmax = fmaxf(lmax, cv);
    }
#pragma unroll
    for (int o = 16; o > 0; o >>= 1) lmax = fmaxf(lmax, __shfl_xor_sync(0xffffffffu, lmax, o));
    if (lane == 0) red[wid] = lmax;
    __syncthreads();
    if (tid == 0) {
        float m = red[0];
#pragma unroll
        for (int q = 1; q < 8; q++) m = fmaxf(m, red[q]);
        s_bcast = m;
    }
    __syncthreads();
    const float cmax = s_bcast;

    float lsum = 0.f;
    for (int i = s + tid; i < e; i += 256) {
        float ev = expf(g_c[i] - cmax);
        g_e[i] = ev;
        lsum += ev;
    }
#pragma unroll
    for (int o = 16; o > 0; o >>= 1) lsum += __shfl_xor_sync(0xffffffffu, lsum, o);
    if (lane == 0) red[wid] = lsum;
    __syncthreads();
    if (tid == 0) {
        float m = 0.f;
#pragma unroll
        for (int q = 0; q < 8; q++) m += red[q];
        s_bcast = m;
    }
    __syncthreads();
    const float denom = s_bcast;
    const float scale = (count > 0) ? ((float)count / denom) : 0.f;

    const int f = tid & 63;
    const int grp = tid >> 6;
    float lm = NEG_INF;
    for (int i = s + grp; i < e; i += 4) {
        float p = g_e[i] * scale;
        lm = fmaxf(lm, p * __ldg(&h3[(size_t)i * 64 + f]));
    }
    __syncthreads();
    __shared__ float pgrp[4][64];
    pgrp[grp][f] = lm;
    __syncthreads();
    if (tid < 64) {
        float m = fmaxf(fmaxf(pgrp[0][tid], pgrp[1][tid]), fmaxf(pgrp[2][tid], pgrp[3][tid]));
        pooled[tid] = (count > 0) ? m : 0.f;
    }
    __syncthreads();

    if (tid < 16) {
        float sj = ba1[tid];
        for (int ff = 0; ff < 64; ff++) sj += pooled[ff] * Wa1[ff * 16 + tid];
        sj = fmaxf(sj, 0.f) * Wa2[tid];
#pragma unroll
        for (int o = 8; o > 0; o >>= 1) sj += __shfl_down_sync(0x0000ffffu, sj, o, 16);
        if (tid == 0) out[g] = sj + ba2[0];
    }
}

// ---------------- launch ----------------
extern "C" void kernel_launch(void* const* d_in, const int* in_sizes, int n_in,
                              void* d_out, int out_size) {
    const float* x     = (const float*)d_in[0];
    const int*   ei    = (const int*)d_in[1];
    const int*   batch = (const int*)d_in[2];
    const float* clo   = (const float*)d_in[3];
    const float* W1l = (const float*)d_in[4];
    const float* b1l = (const float*)d_in[5];
    const float* W1r = (const float*)d_in[6];
    const float* W2l = (const float*)d_in[7];
    const float* b2l = (const float*)d_in[8];
    const float* W2r = (const float*)d_in[9];
    const float* W3l = (const float*)d_in[10];
    const float* b3l = (const float*)d_in[11];
    const float* W3r = (const float*)d_in[12];
    const float* Wc  = (const float*)d_in[13];
    const float* bc  = (const float*)d_in[14];
    const float* Wa1 = (const float*)d_in[15];
    const float* ba1 = (const float*)d_in[16];
    const float* Wa2 = (const float*)d_in[17];
    const float* ba2 = (const float*)d_in[18];
    float* out = (float*)d_out;

    float* h1; cudaGetSymbolAddress((void**)&h1, g_h1);
    float* h2; cudaGetSymbolAddress((void**)&h2, g_h2);
    float* h3; cudaGetSymbolAddress((void**)&h3, g_h3);

    const int TB = 256;
    const int SCAN_BLOCKS = (Nn + 1023) / 1024;  // 98
    const int LBLK = (Nn + 63) / 64;             // 1563

    const int SMEM1 = 2 * 64 * (128 + 4) * sizeof(float);  // 67584
    const int SMEM2 = 2 * 64 * (64 + 4) * sizeof(float);   // 34816
    cudaFuncSetAttribute(fused_sage_layer<128>, cudaFuncAttributeMaxDynamicSharedMemorySize, SMEM1);
    cudaFuncSetAttribute(fused_sage_layer<64>,  cudaFuncAttributeMaxDynamicSharedMemorySize, SMEM2);

    // ---- CSR build (by dst) ----
    zero_deg_kernel<<<(Nn + TB - 1) / TB, TB>>>();
    hist_kernel<<<(Ee + TB - 1) / TB, TB>>>(ei);
    scan_a_kernel<<<SCAN_BLOCKS, 1024>>>();
    scan_c_kernel<<<SCAN_BLOCKS, 1024>>>(SCAN_BLOCKS);
    csr_scatter_kernel<<<(Ee + TB - 1) / TB, TB>>>(ei);

    // ---- fused layers ----
    fused_sage_layer<128><<<LBLK, TB, SMEM1>>>(x,  W1l, b1l, W1r, h1);
    fused_sage_layer<64> <<<LBLK, TB, SMEM2>>>(h1, W2l, b2l, W2r, h2);
    fused_sage_layer<64> <<<LBLK, TB, SMEM2>>>(h2, W3l, b3l, W3r, h3);

    // ---- fused attention pooling + readout ----
    fused_pool_kernel<<<GG, 256>>>((const float4*)clo, Wc, bc, batch, h3,
                                   Wa1, ba1, Wa2, ba2, out);
}

// round 7
// speedup vs baseline: 1.0696x; 1.0696x over previous
#include <cuda_runtime.h>
#include <math.h>

#define Nn   100000
#define Ee   1600000
#define FIN  128
#define HH   64
#define GG   256
#define NEG_INF __int_as_float(0xff800000)

typedef unsigned long long u64;

// ---------------- f32x2 helpers (PTX-only; ptxas never auto-fuses) ----------------
__device__ __forceinline__ u64 pack2(float lo, float hi) {
    u64 r; asm("mov.b64 %0, {%1, %2};" : "=l"(r) : "f"(lo), "f"(hi)); return r;
}
__device__ __forceinline__ void fma2(u64& d, u64 a, u64 b) {
    asm("fma.rn.f32x2 %0, %1, %2, %0;" : "+l"(d) : "l"(a), "l"(b));
}
__device__ __forceinline__ float2 unpack2(u64 v) {
    float2 f; asm("mov.b64 {%0, %1}, %2;" : "=f"(f.x), "=f"(f.y) : "l"(v)); return f;
}

// ---------------- device scratch ----------------
__device__ int   g_deg[Nn];
__device__ int   g_rowptr[Nn];
__device__ int   g_fill[Nn];
__device__ int   g_csr[Ee];
__device__ int   g_bsum[128];
__device__ float g_agg[(size_t)Nn * FIN];
__device__ float g_h1[(size_t)Nn * HH];
__device__ float g_h2[(size_t)Nn * HH];
__device__ float g_h3[(size_t)Nn * HH];
__device__ float g_c[Nn];
__device__ float g_e[Nn];

__device__ __forceinline__ float4 max4(float4 a, float4 b) {
    return make_float4(fmaxf(a.x, b.x), fmaxf(a.y, b.y), fmaxf(a.z, b.z), fmaxf(a.w, b.w));
}
__device__ __forceinline__ float2 max2(float2 a, float2 b) {
    return make_float2(fmaxf(a.x, b.x), fmaxf(a.y, b.y));
}

// ---------------- CSR build ----------------
__global__ void zero_deg_kernel() {
    int i = blockIdx.x * blockDim.x + threadIdx.x;
    if (i < Nn) g_deg[i] = 0;
}

__global__ void hist_kernel(const int* __restrict__ ei) {
    int e = blockIdx.x * blockDim.x + threadIdx.x;
    if (e < Ee) atomicAdd(&g_deg[__ldg(&ei[Ee + e])], 1);
}

__global__ void scan_a_kernel() {
    __shared__ int wsum[32];
    int tid = threadIdx.x;
    int i = blockIdx.x * 1024 + tid;
    int v = (i < Nn) ? g_deg[i] : 0;
    int lane = tid & 31, wid = tid >> 5;
    int x = v;
#pragma unroll
    for (int o = 1; o < 32; o <<= 1) {
        int y = __shfl_up_sync(0xffffffffu, x, o);
        if (lane >= o) x += y;
    }
    if (lane == 31) wsum[wid] = x;
    __syncthreads();
    if (wid == 0) {
        int w = wsum[lane];
        int xx = w;
#pragma unroll
        for (int o = 1; o < 32; o <<= 1) {
            int y = __shfl_up_sync(0xffffffffu, xx, o);
            if (lane >= o) xx += y;
        }
        wsum[lane] = xx - w;
    }
    __syncthreads();
    int excl = x - v + wsum[wid];
    if (i < Nn) g_rowptr[i] = excl;
    if (tid == 1023) g_bsum[blockIdx.x] = excl + v;
}

__global__ void scan_c_kernel(int nb) {
    __shared__ int ws[4];
    __shared__ int soff;
    int tid = threadIdx.x;
    if (tid < 128) {
        int v = (tid < nb && tid < blockIdx.x) ? g_bsum[tid] : 0;
#pragma unroll
        for (int o = 16; o > 0; o >>= 1) v += __shfl_down_sync(0xffffffffu, v, o);
        if ((tid & 31) == 0) ws[tid >> 5] = v;
    }
    __syncthreads();
    if (tid == 0) soff = ws[0] + ws[1] + ws[2] + ws[3];
    __syncthreads();
    int i = blockIdx.x * 1024 + tid;
    if (i < Nn) {
        int r = g_rowptr[i] + soff;
        g_rowptr[i] = r;
        g_fill[i] = r;
    }
}

__global__ void csr_scatter_kernel(const int* __restrict__ ei) {
    int e = blockIdx.x * blockDim.x + threadIdx.x;
    if (e >= Ee) return;
    int src = __ldg(&ei[e]);
    int dst = __ldg(&ei[Ee + e]);
    int pos = atomicAdd(&g_fill[dst], 1);
    g_csr[pos] = src;
}

// ---------------- segmented max (gather, MLP=16) ----------------
// One warp per node, float4 per lane (128 feats).
__global__ void agg_max128(const float4* __restrict__ x4, float4* __restrict__ agg4) {
    int t = blockIdx.x * blockDim.x + threadIdx.x;
    int w = t >> 5;
    if (w >= Nn) return;
    int lane = t & 31;
    int start = g_rowptr[w];
    int d = g_deg[w];
    float4 m = make_float4(NEG_INF, NEG_INF, NEG_INF, NEG_INF);
    int i = 0;
    for (; i + 16 <= d; i += 16) {
        int idx[16];
#pragma unroll
        for (int j = 0; j < 16; j++) idx[j] = g_csr[start + i + j];
        float4 v[16];
#pragma unroll
        for (int j = 0; j < 16; j++) v[j] = __ldg(&x4[(size_t)idx[j] * 32 + lane]);
#pragma unroll
        for (int j = 0; j < 16; j++) m = max4(m, v[j]);
    }
    if (i + 8 <= d) {
        int idx[8];
#pragma unroll
        for (int j = 0; j < 8; j++) idx[j] = g_csr[start + i + j];
        float4 v[8];
#pragma unroll
        for (int j = 0; j < 8; j++) v[j] = __ldg(&x4[(size_t)idx[j] * 32 + lane]);
#pragma unroll
        for (int j = 0; j < 8; j++) m = max4(m, v[j]);
        i += 8;
    }
    if (i + 4 <= d) {
        int idx[4];
#pragma unroll
        for (int j = 0; j < 4; j++) idx[j] = g_csr[start + i + j];
        float4 v[4];
#pragma unroll
        for (int j = 0; j < 4; j++) v[j] = __ldg(&x4[(size_t)idx[j] * 32 + lane]);
#pragma unroll
        for (int j = 0; j < 4; j++) m = max4(m, v[j]);
        i += 4;
    }
    for (; i < d; i++)
        m = max4(m, __ldg(&x4[(size_t)g_csr[start + i] * 32 + lane]));
    if (d == 0) m = make_float4(0.f, 0.f, 0.f, 0.f);
    agg4[(size_t)w * 32 + lane] = m;
}

// One warp per node, float2 per lane (64 feats). Uniform trip count.
__global__ void agg_max64(const float2* __restrict__ h2, float2* __restrict__ agg2) {
    int t = blockIdx.x * blockDim.x + threadIdx.x;
    int w = t >> 5;
    if (w >= Nn) return;
    int lane = t & 31;
    int start = g_rowptr[w];
    int d = g_deg[w];
    float2 m = make_float2(NEG_INF, NEG_INF);
    int i = 0;
    for (; i + 16 <= d; i += 16) {
        int idx[16];
#pragma unroll
        for (int j = 0; j < 16; j++) idx[j] = g_csr[start + i + j];
        float2 v[16];
#pragma unroll
        for (int j = 0; j < 16; j++) v[j] = __ldg(&h2[(size_t)idx[j] * 32 + lane]);
#pragma unroll
        for (int j = 0; j < 16; j++) m = max2(m, v[j]);
    }
    if (i + 8 <= d) {
        int idx[8];
#pragma unroll
        for (int j = 0; j < 8; j++) idx[j] = g_csr[start + i + j];
        float2 v[8];
#pragma unroll
        for (int j = 0; j < 8; j++) v[j] = __ldg(&h2[(size_t)idx[j] * 32 + lane]);
#pragma unroll
        for (int j = 0; j < 8; j++) m = max2(m, v[j]);
        i += 8;
    }
    if (i + 4 <= d) {
        int idx[4];
#pragma unroll
        for (int j = 0; j < 4; j++) idx[j] = g_csr[start + i + j];
        float2 v[4];
#pragma unroll
        for (int j = 0; j < 4; j++) v[j] = __ldg(&h2[(size_t)idx[j] * 32 + lane]);
#pragma unroll
        for (int j = 0; j < 4; j++) m = max2(m, v[j]);
        i += 4;
    }
    for (; i < d; i++)
        m = max2(m, __ldg(&h2[(size_t)g_csr[start + i] * 32 + lane]));
    if (d == 0) m = make_float2(0.f, 0.f);
    agg2[(size_t)w * 32 + lane] = m;
}

// ---------------- fused SAGE layer GEMM (f32x2 packed FMA) ----------------
template <int K>
__global__ void __launch_bounds__(256)
sage_gemm(const float* __restrict__ agg, const float* __restrict__ xin,
          const float* __restrict__ Wl, const float* __restrict__ blv,
          const float* __restrict__ Wr, float* __restrict__ out) {
    __shared__ float sA[64][68];
    __shared__ float sX[64][68];

    const int tid = threadIdx.x;
    const int tx = tid & 15;
    const int ty = tid >> 4;
    const int node0 = blockIdx.x * 64;

    u64 acc[4][2];
#pragma unroll
    for (int i = 0; i < 4; i++) { acc[i][0] = 0ULL; acc[i][1] = 0ULL; }

    for (int k0 = 0; k0 < K; k0 += 64) {
        __syncthreads();
#pragma unroll
        for (int t = tid; t < 64 * 16; t += 256) {
            int nn = t >> 4;
            int ck = t & 15;
            int node = node0 + nn;
            float4 a = make_float4(0.f, 0.f, 0.f, 0.f);
            float4 xv = a;
            if (node < Nn) {
                a  = *(const float4*)&agg[(size_t)node * K + k0 + ck * 4];
                xv = *(const float4*)&xin[(size_t)node * K + k0 + ck * 4];
            }
            *(float4*)&sA[nn][ck * 4] = a;
            *(float4*)&sX[nn][ck * 4] = xv;
        }
        __syncthreads();

#pragma unroll 8
        for (int kk = 0; kk < 64; kk++) {
            const ulonglong2 wl2 = *(const ulonglong2*)&Wl[(size_t)(k0 + kk) * 64 + tx * 4];
            const ulonglong2 wr2 = *(const ulonglong2*)&Wr[(size_t)(k0 + kk) * 64 + tx * 4];
#pragma unroll
            for (int i = 0; i < 4; i++) {
                float a  = sA[ty * 4 + i][kk];
                float xv = sX[ty * 4 + i][kk];
                u64 a2 = pack2(a, a);
                u64 x2 = pack2(xv, xv);
                fma2(acc[i][0], a2, wl2.x);
                fma2(acc[i][1], a2, wl2.y);
                fma2(acc[i][0], x2, wr2.x);
                fma2(acc[i][1], x2, wr2.y);
            }
        }
    }

    const float4 b4 = *(const float4*)&blv[tx * 4];
#pragma unroll
    for (int i = 0; i < 4; i++) {
        int node = node0 + ty * 4 + i;
        if (node < Nn) {
            float2 lo = unpack2(acc[i][0]);
            float2 hi = unpack2(acc[i][1]);
            float4 o;
            o.x = fmaxf(lo.x + b4.x, 0.f);
            o.y = fmaxf(lo.y + b4.y, 0.f);
            o.z = fmaxf(hi.x + b4.z, 0.f);
            o.w = fmaxf(hi.y + b4.w, 0.f);
            *(float4*)&out[(size_t)node * 64 + tx * 4] = o;
        }
    }
}

// ---------------- fused attention pooling: one block per graph ----------------
__global__ void __launch_bounds__(256)
fused_pool_kernel(const float4* __restrict__ clo4, const float* __restrict__ Wc,
                  const float* __restrict__ bc, const int* __restrict__ batch,
                  const float* __restrict__ h3,
                  const float* __restrict__ Wa1, const float* __restrict__ ba1,
                  const float* __restrict__ Wa2, const float* __restrict__ ba2,
                  float* __restrict__ out) {
    const int g = blockIdx.x;
    const int tid = threadIdx.x;
    const int lane = tid & 31, wid = tid >> 5;

    __shared__ int sS, sE;
    __shared__ float red[32];
    __shared__ float s_bcast;
    __shared__ float pooled[64];

    if (tid == 0) {
        int lo = 0, hi = Nn;
        while (lo < hi) { int mid = (lo + hi) >> 1; if (batch[mid] < g) lo = mid + 1; else hi = mid; }
        sS = lo;
        hi = Nn;
        while (lo < hi) { int mid = (lo + hi) >> 1; if (batch[mid] < g + 1) lo = mid + 1; else hi = mid; }
        sE = lo;
    }
    __syncthreads();
    const int s = sS, e = sE;
    const int count = e - s;

    float wc[16];
#pragma unroll
    for (int q = 0; q < 16; q++) wc[q] = Wc[q];
    float bias = bc[0];

    float lmax = NEG_INF;
    for (int i = s + tid; i < e; i += 256) {
        float cv = bias;
#pragma unroll
        for (int q = 0; q < 4; q++) {
            float4 c4 = __ldg(&clo4[(size_t)i * 4 + q]);
            cv += c4.x * wc[q * 4 + 0] + c4.y * wc[q * 4 + 1] + c4.z * wc[q * 4 + 2] + c4.w * wc[q * 4 + 3];
        }
        g_c[i] = cv;
        lmax = fmaxf(lmax, cv);
    }
#pragma unroll
    for (int o = 16; o > 0; o >>= 1) lmax = fmaxf(lmax, __shfl_xor_sync(0xffffffffu, lmax, o));
    if (lane == 0) red[wid] = lmax;
    __syncthreads();
    if (tid == 0) {
        float m = red[0];
#pragma unroll
        for (int q = 1; q < 8; q++) m = fmaxf(m, red[q]);
        s_bcast = m;
    }
    __syncthreads();
    const float cmax = s_bcast;

    float lsum = 0.f;
    for (int i = s + tid; i < e; i += 256) {
        float ev = expf(g_c[i] - cmax);
        g_e[i] = ev;
        lsum += ev;
    }
#pragma unroll
    for (int o = 16; o > 0; o >>= 1) lsum += __shfl_xor_sync(0xffffffffu, lsum, o);
    if (lane == 0) red[wid] = lsum;
    __syncthreads();
    if (tid == 0) {
        float m = 0.f;
#pragma unroll
        for (int q = 0; q < 8; q++) m += red[q];
        s_bcast = m;
    }
    __syncthreads();
    const float denom = s_bcast;
    const float scale = (count > 0) ? ((float)count / denom) : 0.f;

    const int f = tid & 63;
    const int grp = tid >> 6;
    float lm = NEG_INF;
    for (int i = s + grp; i < e; i += 4) {
        float p = g_e[i] * scale;
        lm = fmaxf(lm, p * __ldg(&h3[(size_t)i * 64 + f]));
    }
    __syncthreads();
    __shared__ float pgrp[4][64];
    pgrp[grp][f] = lm;
    __syncthreads();
    if (tid < 64) {
        float m = fmaxf(fmaxf(pgrp[0][tid], pgrp[1][tid]), fmaxf(pgrp[2][tid], pgrp[3][tid]));
        pooled[tid] = (count > 0) ? m : 0.f;
    }
    __syncthreads();

    if (tid < 16) {
        float sj = ba1[tid];
        for (int ff = 0; ff < 64; ff++) sj += pooled[ff] * Wa1[ff * 16 + tid];
        sj = fmaxf(sj, 0.f) * Wa2[tid];
#pragma unroll
        for (int o = 8; o > 0; o >>= 1) sj += __shfl_down_sync(0x0000ffffu, sj, o, 16);
        if (tid == 0) out[g] = sj + ba2[0];
    }
}

// ---------------- launch ----------------
extern "C" void kernel_launch(void* const* d_in, const int* in_sizes, int n_in,
                              void* d_out, int out_size) {
    const float* x     = (const float*)d_in[0];
    const int*   ei    = (const int*)d_in[1];
    const int*   batch = (const int*)d_in[2];
    const float* clo   = (const float*)d_in[3];
    const float* W1l = (const float*)d_in[4];
    const float* b1l = (const float*)d_in[5];
    const float* W1r = (const float*)d_in[6];
    const float* W2l = (const float*)d_in[7];
    const float* b2l = (const float*)d_in[8];
    const float* W2r = (const float*)d_in[9];
    const float* W3l = (const float*)d_in[10];
    const float* b3l = (const float*)d_in[11];
    const float* W3r = (const float*)d_in[12];
    const float* Wc  = (const float*)d_in[13];
    const float* bc  = (const float*)d_in[14];
    const float* Wa1 = (const float*)d_in[15];
    const float* ba1 = (const float*)d_in[16];
    const float* Wa2 = (const float*)d_in[17];
    const float* ba2 = (const float*)d_in[18];
    float* out = (float*)d_out;

    float* agg; cudaGetSymbolAddress((void**)&agg, g_agg);
    float* h1;  cudaGetSymbolAddress((void**)&h1, g_h1);
    float* h2;  cudaGetSymbolAddress((void**)&h2, g_h2);
    float* h3;  cudaGetSymbolAddress((void**)&h3, g_h3);

    const int TB = 256;
    const int SCAN_BLOCKS = (Nn + 1023) / 1024;  // 98

    // ---- CSR build (by dst) ----
    zero_deg_kernel<<<(Nn + TB - 1) / TB, TB>>>();
    hist_kernel<<<(Ee + TB - 1) / TB, TB>>>(ei);
    scan_a_kernel<<<SCAN_BLOCKS, 1024>>>();
    scan_c_kernel<<<SCAN_BLOCKS, 1024>>>(SCAN_BLOCKS);
    csr_scatter_kernel<<<(Ee + TB - 1) / TB, TB>>>(ei);

    // ---- layer 1 (K = 128) ----
    agg_max128<<<(Nn * 32 + TB - 1) / TB, TB>>>((const float4*)x, (float4*)agg);
    sage_gemm<128><<<(Nn + 63) / 64, TB>>>(agg, x, W1l, b1l, W1r, h1);

    // ---- layer 2 (K = 64) ----
    agg_max64<<<(Nn * 32 + TB - 1) / TB, TB>>>((const float2*)h1, (float2*)agg);
    sage_gemm<64><<<(Nn + 63) / 64, TB>>>(agg, h1, W2l, b2l, W2r, h2);

    // ---- layer 3 (K = 64) ----
    agg_max64<<<(Nn * 32 + TB - 1) / TB, TB>>>((const float2*)h2, (float2*)agg);
    sage_gemm<64><<<(Nn + 63) / 64, TB>>>(agg, h2, W3l, b3l, W3r, h3);

    // ---- fused attention pooling + readout ----
    fused_pool_kernel<<<GG, 256>>>((const float4*)clo, Wc, bc, batch, h3,
                                   Wa1, ba1, Wa2, ba2, out);
}

// round 9
// speedup vs baseline: 1.0989x; 1.0274x over previous
#include <cuda_runtime.h>
#include <cuda_fp16.h>
#include <math.h>

#define Nn   100000
#define Ee   1600000
#define FIN  128
#define HH   64
#define GG   256
#define NEG_INF __int_as_float(0xff800000)

typedef unsigned long long u64;

// ---------------- f32x2 helpers (PTX-only; ptxas never auto-fuses) ----------------
__device__ __forceinline__ u64 pack2(float lo, float hi) {
    u64 r; asm("mov.b64 %0, {%1, %2};" : "=l"(r) : "f"(lo), "f"(hi)); return r;
}
__device__ __forceinline__ void fma2(u64& d, u64 a, u64 b) {
    asm("fma.rn.f32x2 %0, %1, %2, %0;" : "+l"(d) : "l"(a), "l"(b));
}
__device__ __forceinline__ float2 unpack2(u64 v) {
    float2 f; asm("mov.b64 {%0, %1}, %2;" : "=f"(f.x), "=f"(f.y) : "l"(v)); return f;
}

// (-inf, -inf) as a half2 bit pattern
__device__ __forceinline__ __half2 h2_neginf() {
    unsigned u = 0xFC00FC00u;
    return *reinterpret_cast<__half2*>(&u);
}

// ---------------- device scratch ----------------
__device__ int     g_deg[Nn];
__device__ int     g_rowptr[Nn];
__device__ int     g_fill[Nn];
__device__ int     g_csr[Ee];
__device__ int     g_bsum[128];
__device__ float   g_agg[(size_t)Nn * FIN];
__device__ __half2 g_h1[(size_t)Nn * 32];   // fp16 hidden states (64 feats = 32 half2)
__device__ __half2 g_h2[(size_t)Nn * 32];
__device__ float   g_h3[(size_t)Nn * HH];   // fp32: feeds pooling
__device__ float   g_c[Nn];
__device__ float   g_e[Nn];

__device__ __forceinline__ float4 max4(float4 a, float4 b) {
    return make_float4(fmaxf(a.x, b.x), fmaxf(a.y, b.y), fmaxf(a.z, b.z), fmaxf(a.w, b.w));
}

// ---------------- CSR build ----------------
__global__ void zero_deg_kernel() {
    int i = blockIdx.x * blockDim.x + threadIdx.x;
    if (i < Nn) g_deg[i] = 0;
}

__global__ void hist_kernel(const int* __restrict__ ei) {
    int e = blockIdx.x * blockDim.x + threadIdx.x;
    if (e < Ee) atomicAdd(&g_deg[__ldg(&ei[Ee + e])], 1);
}

__global__ void scan_a_kernel() {
    __shared__ int wsum[32];
    int tid = threadIdx.x;
    int i = blockIdx.x * 1024 + tid;
    int v = (i < Nn) ? g_deg[i] : 0;
    int lane = tid & 31, wid = tid >> 5;
    int x = v;
#pragma unroll
    for (int o = 1; o < 32; o <<= 1) {
        int y = __shfl_up_sync(0xffffffffu, x, o);
        if (lane >= o) x += y;
    }
    if (lane == 31) wsum[wid] = x;
    __syncthreads();
    if (wid == 0) {
        int w = wsum[lane];
        int xx = w;
#pragma unroll
        for (int o = 1; o < 32; o <<= 1) {
            int y = __shfl_up_sync(0xffffffffu, xx, o);
            if (lane >= o) xx += y;
        }
        wsum[lane] = xx - w;
    }
    __syncthreads();
    int excl = x - v + wsum[wid];
    if (i < Nn) g_rowptr[i] = excl;
    if (tid == 1023) g_bsum[blockIdx.x] = excl + v;
}

__global__ void scan_c_kernel(int nb) {
    __shared__ int ws[4];
    __shared__ int soff;
    int tid = threadIdx.x;
    if (tid < 128) {
        int v = (tid < nb && tid < blockIdx.x) ? g_bsum[tid] : 0;
#pragma unroll
        for (int o = 16; o > 0; o >>= 1) v += __shfl_down_sync(0xffffffffu, v, o);
        if ((tid & 31) == 0) ws[tid >> 5] = v;
    }
    __syncthreads();
    if (tid == 0) soff = ws[0] + ws[1] + ws[2] + ws[3];
    __syncthreads();
    int i = blockIdx.x * 1024 + tid;
    if (i < Nn) {
        int r = g_rowptr[i] + soff;
        g_rowptr[i] = r;
        g_fill[i] = r;
    }
}

__global__ void csr_scatter_kernel(const int* __restrict__ ei) {
    int e = blockIdx.x * blockDim.x + threadIdx.x;
    if (e >= Ee) return;
    int src = __ldg(&ei[e]);
    int dst = __ldg(&ei[Ee + e]);
    int pos = atomicAdd(&g_fill[dst], 1);
    g_csr[pos] = src;
}

// ---------------- segmented max (gather) ----------------
// Layer 1: one warp per node, float4 per lane (128 fp32 feats).
__global__ void agg_max128(const float4* __restrict__ x4, float4* __restrict__ agg4) {
    int t = blockIdx.x * blockDim.x + threadIdx.x;
    int w = t >> 5;
    if (w >= Nn) return;
    int lane = t & 31;
    int start = g_rowptr[w];
    int d = g_deg[w];
    float4 m = make_float4(NEG_INF, NEG_INF, NEG_INF, NEG_INF);
    int i = 0;
    for (; i + 16 <= d; i += 16) {
        int idx[16];
#pragma unroll
        for (int j = 0; j < 16; j++) idx[j] = g_csr[start + i + j];
        float4 v[16];
#pragma unroll
        for (int j = 0; j < 16; j++) v[j] = __ldg(&x4[(size_t)idx[j] * 32 + lane]);
#pragma unroll
        for (int j = 0; j < 16; j++) m = max4(m, v[j]);
    }
    if (i + 8 <= d) {
        int idx[8];
#pragma unroll
        for (int j = 0; j < 8; j++) idx[j] = g_csr[start + i + j];
        float4 v[8];
#pragma unroll
        for (int j = 0; j < 8; j++) v[j] = __ldg(&x4[(size_t)idx[j] * 32 + lane]);
#pragma unroll
        for (int j = 0; j < 8; j++) m = max4(m, v[j]);
        i += 8;
    }
    if (i + 4 <= d) {
        int idx[4];
#pragma unroll
        for (int j = 0; j < 4; j++) idx[j] = g_csr[start + i + j];
        float4 v[4];
#pragma unroll
        for (int j = 0; j < 4; j++) v[j] = __ldg(&x4[(size_t)idx[j] * 32 + lane]);
#pragma unroll
        for (int j = 0; j < 4; j++) m = max4(m, v[j]);
        i += 4;
    }
    for (; i < d; i++)
        m = max4(m, __ldg(&x4[(size_t)g_csr[start + i] * 32 + lane]));
    if (d == 0) m = make_float4(0.f, 0.f, 0.f, 0.f);
    agg4[(size_t)w * 32 + lane] = m;
}

// Layers 2/3: one warp per node, one half2 per lane (64 fp16 feats; exact max selection).
__global__ void agg_max64_h(const __half2* __restrict__ h2, float2* __restrict__ agg2) {
    int t = blockIdx.x * blockDim.x + threadIdx.x;
    int w = t >> 5;
    if (w >= Nn) return;
    int lane = t & 31;
    int start = g_rowptr[w];
    int d = g_deg[w];
    __half2 m = h2_neginf();
    int i = 0;
    for (; i + 16 <= d; i += 16) {
        int idx[16];
#pragma unroll
        for (int j = 0; j < 16; j++) idx[j] = g_csr[start + i + j];
        __half2 v[16];
#pragma unroll
        for (int j = 0; j < 16; j++) v[j] = __ldg(&h2[(size_t)idx[j] * 32 + lane]);
#pragma unroll
        for (int j = 0; j < 16; j++) m = __hmax2(m, v[j]);
    }
    if (i + 8 <= d) {
        int idx[8];
#pragma unroll
        for (int j = 0; j < 8; j++) idx[j] = g_csr[start + i + j];
        __half2 v[8];
#pragma unroll
        for (int j = 0; j < 8; j++) v[j] = __ldg(&h2[(size_t)idx[j] * 32 + lane]);
#pragma unroll
        for (int j = 0; j < 8; j++) m = __hmax2(m, v[j]);
        i += 8;
    }
    if (i + 4 <= d) {
        int idx[4];
#pragma unroll
        for (int j = 0; j < 4; j++) idx[j] = g_csr[start + i + j];
        __half2 v[4];
#pragma unroll
        for (int j = 0; j < 4; j++) v[j] = __ldg(&h2[(size_t)idx[j] * 32 + lane]);
#pragma unroll
        for (int j = 0; j < 4; j++) m = __hmax2(m, v[j]);
        i += 4;
    }
    for (; i < d; i++)
        m = __hmax2(m, __ldg(&h2[(size_t)g_csr[start + i] * 32 + lane]));
    float2 f = (d == 0) ? make_float2(0.f, 0.f) : __half22float2(m);
    agg2[(size_t)w * 32 + lane] = f;
}

// ---------------- fused SAGE layer GEMM (f32x2 packed FMA) ----------------
// XH: xin is __half2 (64 feats). OH: output written as __half2.
template <int K, bool XH, bool OH>
__global__ void __launch_bounds__(256)
sage_gemm(const float* __restrict__ agg, const void* __restrict__ xin_v,
          const float* __restrict__ Wl, const float* __restrict__ blv,
          const float* __restrict__ Wr, void* __restrict__ out_v) {
    __shared__ float sA[64][68];
    __shared__ float sX[64][68];

    const int tid = threadIdx.x;
    const int tx = tid & 15;
    const int ty = tid >> 4;
    const int node0 = blockIdx.x * 64;

    u64 acc[4][2];
#pragma unroll
    for (int i = 0; i < 4; i++) { acc[i][0] = 0ULL; acc[i][1] = 0ULL; }

    for (int k0 = 0; k0 < K; k0 += 64) {
        __syncthreads();
#pragma unroll
        for (int t = tid; t < 64 * 16; t += 256) {
            int nn = t >> 4;
            int ck = t & 15;
            int node = node0 + nn;
            float4 a = make_float4(0.f, 0.f, 0.f, 0.f);
            float4 xv = a;
            if (node < Nn) {
                a = *(const float4*)&agg[(size_t)node * K + k0 + ck * 4];
                if (XH) {
                    const __half2* xh = (const __half2*)xin_v;
                    uint2 raw = *(const uint2*)&xh[(size_t)node * 32 + ck * 2];
                    float2 lo = __half22float2(*(const __half2*)&raw.x);
                    float2 hi = __half22float2(*(const __half2*)&raw.y);
                    xv = make_float4(lo.x, lo.y, hi.x, hi.y);
                } else {
                    xv = *(const float4*)&((const float*)xin_v)[(size_t)node * K + k0 + ck * 4];
                }
            }
            *(float4*)&sA[nn][ck * 4] = a;
            *(float4*)&sX[nn][ck * 4] = xv;
        }
        __syncthreads();

#pragma unroll 8
        for (int kk = 0; kk < 64; kk++) {
            const ulonglong2 wl2 = *(const ulonglong2*)&Wl[(size_t)(k0 + kk) * 64 + tx * 4];
            const ulonglong2 wr2 = *(const ulonglong2*)&Wr[(size_t)(k0 + kk) * 64 + tx * 4];
#pragma unroll
            for (int i = 0; i < 4; i++) {
                float a  = sA[ty * 4 + i][kk];
                float xv = sX[ty * 4 + i][kk];
                u64 a2 = pack2(a, a);
                u64 x2 = pack2(xv, xv);
                fma2(acc[i][0], a2, wl2.x);
                fma2(acc[i][1], a2, wl2.y);
                fma2(acc[i][0], x2, wr2.x);
                fma2(acc[i][1], x2, wr2.y);
            }
        }
    }

    const float4 b4 = *(const float4*)&blv[tx * 4];
#pragma unroll
    for (int i = 0; i < 4; i++) {
        int node = node0 + ty * 4 + i;
        if (node < Nn) {
            float2 lo = unpack2(acc[i][0]);
            float2 hi = unpack2(acc[i][1]);
            float4 o;
            o.x = fmaxf(lo.x + b4.x, 0.f);
            o.y = fmaxf(lo.y + b4.y, 0.f);
            o.z = fmaxf(hi.x + b4.z, 0.f);
            o.w = fmaxf(hi.y + b4.w, 0.f);
            if (OH) {
                __half2* oh = (__half2*)out_v;
                uint2 w2;
                *(__half2*)&w2.x = __floats2half2_rn(o.x, o.y);
                *(__half2*)&w2.y = __floats2half2_rn(o.z, o.w);
                *(uint2*)&oh[(size_t)node * 32 + tx * 2] = w2;
            } else {
                *(float4*)&((float*)out_v)[(size_t)node * 64 + tx * 4] = o;
            }
        }
    }
}

// ---------------- fused attention pooling: one block per graph ----------------
__global__ void __launch_bounds__(256)
fused_pool_kernel(const float4* __restrict__ clo4, const float* __restrict__ Wc,
                  const float* __restrict__ bc, const int* __restrict__ batch,
                  const float* __restrict__ h3,
                  const float* __restrict__ Wa1, const float* __restrict__ ba1,
                  const float* __restrict__ Wa2, const float* __restrict__ ba2,
                  float* __restrict__ out) {
    const int g = blockIdx.x;
    const int tid = threadIdx.x;
    const int lane = tid & 31, wid = tid >> 5;

    __shared__ int sS, sE;
    __shared__ float red[32];
    __shared__ float s_bcast;
    __shared__ float pooled[64];

    if (tid == 0) {
        int lo = 0, hi = Nn;
        while (lo < hi) { int mid = (lo + hi) >> 1; if (batch[mid] < g) lo = mid + 1; else hi = mid; }
        sS = lo;
        hi = Nn;
        while (lo < hi) { int mid = (lo + hi) >> 1; if (batch[mid] < g + 1) lo = mid + 1; else hi = mid; }
        sE = lo;
    }
    __syncthreads();
    const int s = sS, e = sE;
    const int count = e - s;

    float wc[16];
#pragma unroll
    for (int q = 0; q < 16; q++) wc[q] = Wc[q];
    float bias = bc[0];

    float lmax = NEG_INF;
    for (int i = s + tid; i < e; i += 256) {
        float cv = bias;
#pragma unroll
        for (int q = 0; q < 4; q++) {
            float4 c4 = __ldg(&clo4[(size_t)i * 4 + q]);
            cv += c4.x * wc[q * 4 + 0] + c4.y * wc[q * 4 + 1] + c4.z * wc[q * 4 + 2] + c4.w * wc[q * 4 + 3];
        }
        g_c[i] = cv;
        lmax = fmaxf(lmax, cv);
    }
#pragma unroll
    for (int o = 16; o > 0; o >>= 1) lmax = fmaxf(lmax, __shfl_xor_sync(0xffffffffu, lmax, o));
    if (lane == 0) red[wid] = lmax;
    __syncthreads();
    if (tid == 0) {
        float m = red[0];
#pragma unroll
        for (int q = 1; q < 8; q++) m = fmaxf(m, red[q]);
        s_bcast = m;
    }
    __syncthreads();
    const float cmax = s_bcast;

    float lsum = 0.f;
    for (int i = s + tid; i < e; i += 256) {
        float ev = expf(g_c[i] - cmax);
        g_e[i] = ev;
        lsum += ev;
    }
#pragma unroll
    for (int o = 16; o > 0; o >>= 1) lsum += __shfl_xor_sync(0xffffffffu, lsum, o);
    if (lane == 0) red[wid] = lsum;
    __syncthreads();
    if (tid == 0) {
        float m = 0.f;
#pragma unroll
        for (int q = 0; q < 8; q++) m += red[q];
        s_bcast = m;
    }
    __syncthreads();
    const float denom = s_bcast;
    const float scale = (count > 0) ? ((float)count / denom) : 0.f;

    const int f = tid & 63;
    const int grp = tid >> 6;
    float lm = NEG_INF;
    for (int i = s + grp; i < e; i += 4) {
        float p = g_e[i] * scale;
        lm = fmaxf(lm, p * __ldg(&h3[(size_t)i * 64 + f]));
    }
    __syncthreads();
    __shared__ float pgrp[4][64];
    pgrp[grp][f] = lm;
    __syncthreads();
    if (tid < 64) {
        float m = fmaxf(fmaxf(pgrp[0][tid], pgrp[1][tid]), fmaxf(pgrp[2][tid], pgrp[3][tid]));
        pooled[tid] = (count > 0) ? m : 0.f;
    }
    __syncthreads();

    if (tid < 16) {
        float sj = ba1[tid];
        for (int ff = 0; ff < 64; ff++) sj += pooled[ff] * Wa1[ff * 16 + tid];
        sj = fmaxf(sj, 0.f) * Wa2[tid];
#pragma unroll
        for (int o = 8; o > 0; o >>= 1) sj += __shfl_down_sync(0x0000ffffu, sj, o, 16);
        if (tid == 0) out[g] = sj + ba2[0];
    }
}

// ---------------- launch ----------------
extern "C" void kernel_launch(void* const* d_in, const int* in_sizes, int n_in,
                              void* d_out, int out_size) {
    const float* x     = (const float*)d_in[0];
    const int*   ei    = (const int*)d_in[1];
    const int*   batch = (const int*)d_in[2];
    const float* clo   = (const float*)d_in[3];
    const float* W1l = (const float*)d_in[4];
    const float* b1l = (const float*)d_in[5];
    const float* W1r = (const float*)d_in[6];
    const float* W2l = (const float*)d_in[7];
    const float* b2l = (const float*)d_in[8];
    const float* W2r = (const float*)d_in[9];
    const float* W3l = (const float*)d_in[10];
    const float* b3l = (const float*)d_in[11];
    const float* W3r = (const float*)d_in[12];
    const float* Wc  = (const float*)d_in[13];
    const float* bc  = (const float*)d_in[14];
    const float* Wa1 = (const float*)d_in[15];
    const float* ba1 = (const float*)d_in[16];
    const float* Wa2 = (const float*)d_in[17];
    const float* ba2 = (const float*)d_in[18];
    float* out = (float*)d_out;

    float*   agg; cudaGetSymbolAddress((void**)&agg, g_agg);
    __half2* h1;  cudaGetSymbolAddress((void**)&h1, g_h1);
    __half2* h2;  cudaGetSymbolAddress((void**)&h2, g_h2);
    float*   h3;  cudaGetSymbolAddress((void**)&h3, g_h3);

    const int TB = 256;
    const int SCAN_BLOCKS = (Nn + 1023) / 1024;  // 98
    const int GBLK = (Nn + 63) / 64;             // 1563

    // ---- CSR build (by dst) ----
    zero_deg_kernel<<<(Nn + TB - 1) / TB, TB>>>();
    hist_kernel<<<(Ee + TB - 1) / TB, TB>>>(ei);
    scan_a_kernel<<<SCAN_BLOCKS, 1024>>>();
    scan_c_kernel<<<SCAN_BLOCKS, 1024>>>(SCAN_BLOCKS);
    csr_scatter_kernel<<<(Ee + TB - 1) / TB, TB>>>(ei);

    // ---- layer 1 (K = 128, fp32 in, fp16 out) ----
    agg_max128<<<(Nn * 32 + TB - 1) / TB, TB>>>((const float4*)x, (float4*)agg);
    sage_gemm<128, false, true><<<GBLK, TB>>>(agg, x, W1l, b1l, W1r, h1);

    // ---- layer 2 (K = 64, fp16 in, fp16 out) ----
    agg_max64_h<<<(Nn * 32 + TB - 1) / TB, TB>>>(h1, (float2*)agg);
    sage_gemm<64, true, true><<<GBLK, TB>>>(agg, h1, W2l, b2l, W2r, h2);

    // ---- layer 3 (K = 64, fp16 in, fp32 out) ----
    agg_max64_h<<<(Nn * 32 + TB - 1) / TB, TB>>>(h2, (float2*)agg);
    sage_gemm<64, true, false><<<GBLK, TB>>>(agg, h2, W3l, b3l, W3r, h3);

    // ---- fused attention pooling + readout ----
    fused_pool_kernel<<<GG, 256>>>((const float4*)clo, Wc, bc, batch, h3,
                                   Wa1, ba1, Wa2, ba2, out);
}